// round 16
// baseline (speedup 1.0000x reference)
#include <cuda_runtime.h>
#include <cuda_bf16.h>
#include <math.h>
#include <stdint.h>

static constexpr int kHeads = 16;
static constexpr int kD     = 64;
static constexpr int kB     = 2;
static constexpr int kN     = 2048;
static constexpr int kDim   = 1024;
static constexpr int kRows  = kB * kN;          // 4096
static constexpr int kQkvN  = 3 * kHeads * kD;  // 3072
static constexpr int kKV    = kN + 4;           // 2052

// ---------------- scratch (device globals; no allocation) ----------------
__device__ __nv_bfloat16 g_x16[(size_t)kRows * kDim];
__device__ __nv_bfloat16 g_wn_qkv16[(size_t)kQkvN * kDim];
__device__ __nv_bfloat16 g_wn_out16[(size_t)kDim * kDim];
__device__ __nv_bfloat16 g_attn16[(size_t)kRows * kDim];
__device__ float g_qkv[(size_t)kRows * kQkvN];

__device__ __forceinline__ uint32_t bfpack(float lo, float hi) {
  uint32_t r;
  asm("cvt.rn.bf16x2.f32 %0, %1, %2;" : "=r"(r) : "f"(hi), "f"(lo));
  return r;
}

__device__ __forceinline__ void cp16(uint32_t* s, const void* g) {
  uint32_t sa = (uint32_t)__cvta_generic_to_shared(s);
  asm volatile("cp.async.cg.shared.global [%0], [%1], 16;\n" :: "r"(sa), "l"(g));
}

__device__ __forceinline__ void mma_bf16(float* d, const uint32_t* a, const uint32_t* b) {
  asm volatile(
      "mma.sync.aligned.m16n8k16.row.col.f32.bf16.bf16.f32 "
      "{%0,%1,%2,%3}, {%4,%5,%6,%7}, {%8,%9}, {%0,%1,%2,%3};\n"
      : "+f"(d[0]), "+f"(d[1]), "+f"(d[2]), "+f"(d[3])
      : "r"(a[0]), "r"(a[1]), "r"(a[2]), "r"(a[3]), "r"(b[0]), "r"(b[1]));
}

__device__ __forceinline__ void ldsm4(uint32_t* r, uint32_t addr) {
  asm volatile("ldmatrix.sync.aligned.m8n8.x4.shared.b16 {%0,%1,%2,%3}, [%4];"
               : "=r"(r[0]), "=r"(r[1]), "=r"(r[2]), "=r"(r[3]) : "r"(addr));
}

// ---------------- convert x to bf16 ----------------
__global__ __launch_bounds__(256) void conv_x_kernel(const float* __restrict__ x) {
  const int i = blockIdx.x * 256 + threadIdx.x;  // one float4 each
  float4 v = ((const float4*)x)[i];
  ((uint2*)g_x16)[i] = make_uint2(bfpack(v.x, v.y), bfpack(v.z, v.w));
}

// ---------------- weight row l2-norm -> bf16 ----------------
__global__ __launch_bounds__(256) void norm_rows_kernel(const float* __restrict__ w, int which) {
  __nv_bfloat16* wn = which ? g_wn_out16 : g_wn_qkv16;
  const int row = blockIdx.x;
  const int t = threadIdx.x;  // 256 threads, 1024 cols -> 1 float4 each
  float4 v = ((const float4*)(w + (size_t)row * kDim))[t];
  float ss = v.x * v.x + v.y * v.y + v.z * v.z + v.w * v.w;
#pragma unroll
  for (int off = 16; off; off >>= 1) ss += __shfl_xor_sync(0xffffffffu, ss, off);
  __shared__ float red[8];
  if ((t & 31) == 0) red[t >> 5] = ss;
  __syncthreads();
  float tot = red[0] + red[1] + red[2] + red[3] + red[4] + red[5] + red[6] + red[7];
  float sc = 1.0f / (fmaxf(sqrtf(tot), 1e-4f) * 32.0f);  // 32 = sqrt(1024)
  ((uint2*)(wn + (size_t)row * kDim))[t] =
      make_uint2(bfpack(v.x * sc, v.y * sc), bfpack(v.z * sc, v.w * sc));
}

// ---------------- bf16 tensor-core GEMM: C[m,n] = sum_k A[m,k]*B[n,k] ----------------
// 128x128 CTA tile, BK=64 halves, 3-stage cp.async ring (ONE syncthreads per
// iter: compute stage kb%3 while filling stage (kb+2)%3 == stage computed last
// iter, protected by this iter's sync). 8 warps (2x4), warp tile 64x32 = 4x4
// m16n8k16 frags via ldmatrix.x4 (stride 36 uints -> conflict-free).
static constexpr int kGemmSmemBytes = 6 * 4608 * 4;  // 110592

template <int NCOLS, bool FUSE>
__global__ __launch_bounds__(256, 2) void gemm_bf16_kernel(const __nv_bfloat16* __restrict__ A,
                                                           const __nv_bfloat16* __restrict__ Bw,
                                                           float* __restrict__ C,
                                                           const float* __restrict__ resid) {
  extern __shared__ uint32_t sg[];
  uint32_t* AsBuf[3] = {sg, sg + 4608, sg + 9216};
  uint32_t* BsBuf[3] = {sg + 13824, sg + 18432, sg + 23040};

  const int t = threadIdx.x, lane = t & 31, warp = t >> 5;
  const int wm = warp >> 2, wn = warp & 3;
  const int m0 = blockIdx.y * 128, n0 = blockIdx.x * 128;
  const int srow = t >> 1, sc2 = (t & 1) * 16;  // half2 col offset
  const __nv_bfloat16* gA = A + (size_t)(m0 + srow) * kDim + sc2 * 2;
  const __nv_bfloat16* gB = Bw + (size_t)(n0 + srow) * kDim + sc2 * 2;

  auto prefetch = [&](int s, int k0) {  // k0 in halves
    uint32_t* da = AsBuf[s] + srow * 36 + sc2;
    uint32_t* db = BsBuf[s] + srow * 36 + sc2;
#pragma unroll
    for (int u = 0; u < 4; u++) {
      cp16(da + u * 4, gA + k0 + u * 8);
      cp16(db + u * 4, gB + k0 + u * 8);
    }
  };

  float acc[4][4][4];
#pragma unroll
  for (int mt = 0; mt < 4; mt++)
#pragma unroll
    for (int nt = 0; nt < 4; nt++)
#pragma unroll
      for (int r = 0; r < 4; r++) acc[mt][nt][r] = 0.f;

  prefetch(0, 0);
  asm volatile("cp.async.commit_group;\n");
  prefetch(1, 64);
  asm volatile("cp.async.commit_group;\n");

  const int qr = lane >> 2, qc = lane & 3;
  // ldmatrix lane offsets (uint units, relative to tile base):
  const int a_off = (wm * 64 + (lane & 7) + ((lane >> 3) & 1) * 8) * 36 + (lane >> 4) * 4;
  const int b_off = (wn * 32 + (lane & 7) + ((lane >> 4) & 1) * 8) * 36 + ((lane >> 3) & 1) * 4;

  int cur = 0, nxt = 2;
#pragma unroll 1
  for (int kb = 0; kb < 16; kb++) {  // 16 x 64 halves = 1024
    asm volatile("cp.async.wait_group 1;\n");
    __syncthreads();  // stage `cur` visible; stage `nxt` (computed last iter) free

    if (kb + 2 < 16) prefetch(nxt, (kb + 2) * 64);
    asm volatile("cp.async.commit_group;\n");

    const uint32_t baseA = (uint32_t)__cvta_generic_to_shared(AsBuf[cur]);
    const uint32_t baseB = (uint32_t)__cvta_generic_to_shared(BsBuf[cur]);
#pragma unroll
    for (int kt = 0; kt < 4; kt++) {  // 4 x k16
      uint32_t af[4][4], bq[2][4];
      ldsm4(bq[0], baseB + 4u * (b_off + kt * 8));
      ldsm4(bq[1], baseB + 4u * (b_off + 16 * 36 + kt * 8));
#pragma unroll
      for (int mt = 0; mt < 4; mt++)
        ldsm4(af[mt], baseA + 4u * (a_off + mt * 16 * 36 + kt * 8));
#pragma unroll
      for (int mt = 0; mt < 4; mt++)
#pragma unroll
        for (int nt = 0; nt < 4; nt++)
          mma_bf16(acc[mt][nt], af[mt], &bq[nt >> 1][(nt & 1) * 2]);
    }
    cur = (cur == 2) ? 0 : cur + 1;
    nxt = (nxt == 2) ? 0 : nxt + 1;
  }

  const float C_OUT = 0.91914503001805780f;  // 0.7/sqrt(0.58)
  const float C_X   = 0.39391929857916763f;  // 0.3/sqrt(0.58)
#pragma unroll
  for (int mt = 0; mt < 4; mt++)
#pragma unroll
    for (int nt = 0; nt < 4; nt++) {
      const int r = m0 + wm * 64 + mt * 16 + qr;
      const int cb = n0 + wn * 32 + nt * 8 + qc * 2;
      const float* a4 = acc[mt][nt];
      if (FUSE) {
        float2 r0 = *(const float2*)&resid[(size_t)r * NCOLS + cb];
        float2 r1 = *(const float2*)&resid[(size_t)(r + 8) * NCOLS + cb];
        *(float2*)&C[(size_t)r * NCOLS + cb] =
            make_float2(a4[0] * C_OUT + r0.x * C_X, a4[1] * C_OUT + r0.y * C_X);
        *(float2*)&C[(size_t)(r + 8) * NCOLS + cb] =
            make_float2(a4[2] * C_OUT + r1.x * C_X, a4[3] * C_OUT + r1.y * C_X);
      } else {
        *(float2*)&C[(size_t)r * NCOLS + cb] = make_float2(a4[0], a4[1]);
        *(float2*)&C[(size_t)(r + 8) * NCOLS + cb] = make_float2(a4[2], a4[3]);
      }
    }
}

// ---------------- bf16 tensor-core flash attention, pixel-norm fused ----------------
// (R14 structure — blocking KV loads; the register-prefetch variant measured
// ~23us SLOWER due to register pressure, so it was reverted.)
static constexpr int kAttnSmemBytes = 4608 * 4;  // 18432

__global__ __launch_bounds__(256, 2) void attn_kernel(const float* __restrict__ memkv) {
  extern __shared__ uint32_t su[];  // 4608 uints
  uint32_t* Ks2 = su;          // [64][36]
  uint32_t* Vt2 = su + 2304;   // [64][36]

  const float* __restrict__ qkv = g_qkv;
  const int t = threadIdx.x;
  const int lane = t & 31, warp = t >> 5;
  const int qr = lane >> 2, qc = lane & 3;
  const int qt = blockIdx.x;
  const int b = blockIdx.y >> 4, h = blockIdx.y & 15;

  // ---- stage + pixel-norm Q (128 rows x 32 half2, stride 36, spans Ks2+Vt2) ----
  {
    const int rr = t >> 1, half = t & 1;  // 2 threads per row, 32 cols each
    const float* qp = qkv + (size_t)(b * kN + qt * 128 + rr) * kQkvN + h * 64 + half * 32;
    float4 q4[8];
    float ss = 0.f;
#pragma unroll
    for (int u = 0; u < 8; u++) {
      q4[u] = *(const float4*)(qp + u * 4);
      ss += q4[u].x * q4[u].x + q4[u].y * q4[u].y + q4[u].z * q4[u].z + q4[u].w * q4[u].w;
    }
    ss += __shfl_xor_sync(0xffffffffu, ss, 1);
    const float sc = 1.0f / fmaxf(sqrtf(ss), 1e-4f);
    uint32_t* dst = su + rr * 36 + half * 16;
#pragma unroll
    for (int u = 0; u < 4; u++) {
      uint4 pk;
      pk.x = bfpack(q4[u * 2].x * sc, q4[u * 2].y * sc);
      pk.y = bfpack(q4[u * 2].z * sc, q4[u * 2].w * sc);
      pk.z = bfpack(q4[u * 2 + 1].x * sc, q4[u * 2 + 1].y * sc);
      pk.w = bfpack(q4[u * 2 + 1].z * sc, q4[u * 2 + 1].w * sc);
      *(uint4*)(dst + u * 4) = pk;
    }
  }
  __syncthreads();

  // ---- Q A-fragments -> registers (held for entire kernel) ----
  uint32_t qf[4][4];
  {
    const int m = warp * 16 + qr;
#pragma unroll
    for (int kc = 0; kc < 4; kc++) {
      qf[kc][0] = su[m * 36 + kc * 8 + qc];
      qf[kc][1] = su[(m + 8) * 36 + kc * 8 + qc];
      qf[kc][2] = su[m * 36 + kc * 8 + qc + 4];
      qf[kc][3] = su[(m + 8) * 36 + kc * 8 + qc + 4];
    }
  }

  float oacc[8][4];
#pragma unroll
  for (int nt = 0; nt < 8; nt++)
#pragma unroll
    for (int r = 0; r < 4; r++) oacc[nt][r] = 0.f;
  float mr0 = -INFINITY, mr1 = -INFINITY, lr0 = 0.f, lr1 = 0.f;

  const int pr = t >> 3, lq8 = t & 7;  // kv loader: pair row 0..31, 8 d-threads/row

  for (int j0 = 0; j0 < kKV; j0 += 64) {
    const int L = (kKV - j0 < 64) ? (kKV - j0) : 64;

    // load two adjacent kv rows (2pr, 2pr+1), 8 d values each at d0 = lq8*8
    float ka[8], kb8[8], va[8], vb[8];
    float sska = 0.f, sskb = 0.f, ssva = 0.f, ssvb = 0.f;
    auto loadrow = [&](int j, float* kk, float* vv, float& ssk, float& ssv) {
      if (j < kKV) {
        const float *kp, *vp;
        if (j < 4) {
          kp = memkv + (size_t)(h * 4 + j) * 64 + lq8 * 8;
          vp = memkv + (size_t)((kHeads + h) * 4 + j) * 64 + lq8 * 8;
        } else {
          const size_t base = (size_t)(b * kN + (j - 4)) * kQkvN + h * 64 + lq8 * 8;
          kp = qkv + base + 1024;
          vp = qkv + base + 2048;
        }
#pragma unroll
        for (int u = 0; u < 2; u++) {
          float4 k4 = *(const float4*)(kp + u * 4);
          float4 v4 = *(const float4*)(vp + u * 4);
          kk[u * 4 + 0] = k4.x; kk[u * 4 + 1] = k4.y; kk[u * 4 + 2] = k4.z; kk[u * 4 + 3] = k4.w;
          vv[u * 4 + 0] = v4.x; vv[u * 4 + 1] = v4.y; vv[u * 4 + 2] = v4.z; vv[u * 4 + 3] = v4.w;
          ssk += k4.x * k4.x + k4.y * k4.y + k4.z * k4.z + k4.w * k4.w;
          ssv += v4.x * v4.x + v4.y * v4.y + v4.z * v4.z + v4.w * v4.w;
        }
      } else {
#pragma unroll
        for (int u = 0; u < 8; u++) { kk[u] = 0.f; vv[u] = 0.f; }
      }
    };
    loadrow(j0 + 2 * pr,     ka,  va, sska, ssva);
    loadrow(j0 + 2 * pr + 1, kb8, vb, sskb, ssvb);
#pragma unroll
    for (int off = 1; off <= 4; off <<= 1) {  // reduce over the 8 d-threads
      sska += __shfl_xor_sync(0xffffffffu, sska, off);
      sskb += __shfl_xor_sync(0xffffffffu, sskb, off);
      ssva += __shfl_xor_sync(0xffffffffu, ssva, off);
      ssvb += __shfl_xor_sync(0xffffffffu, ssvb, off);
    }
    const float ska = 8.0f / fmaxf(sqrtf(sska), 1e-4f);
    const float skb = 8.0f / fmaxf(sqrtf(sskb), 1e-4f);
    const float sva = 8.0f / fmaxf(sqrtf(ssva), 1e-4f);
    const float svb = 8.0f / fmaxf(sqrtf(ssvb), 1e-4f);

    __syncthreads();  // previous tile (or Q stage/frag reads) fully consumed
    {
      // K: row-major [kv][dpair]
      uint4 p0, p1;
      p0.x = bfpack(ka[0] * ska, ka[1] * ska);
      p0.y = bfpack(ka[2] * ska, ka[3] * ska);
      p0.z = bfpack(ka[4] * ska, ka[5] * ska);
      p0.w = bfpack(ka[6] * ska, ka[7] * ska);
      p1.x = bfpack(kb8[0] * skb, kb8[1] * skb);
      p1.y = bfpack(kb8[2] * skb, kb8[3] * skb);
      p1.z = bfpack(kb8[4] * skb, kb8[5] * skb);
      p1.w = bfpack(kb8[6] * skb, kb8[7] * skb);
      *(uint4*)(Ks2 + (2 * pr) * 36 + lq8 * 4) = p0;
      *(uint4*)(Ks2 + (2 * pr + 1) * 36 + lq8 * 4) = p1;
      // V: transposed [d][kvpair], swizzled col = pr ^ (lq8<<2)
      const int col = pr ^ (lq8 << 2);
#pragma unroll
      for (int i = 0; i < 8; i++)
        Vt2[(lq8 * 8 + i) * 36 + col] = bfpack(va[i] * sva, vb[i] * svb);
    }
    __syncthreads();

    // ---- S = Qn @ Kn^T (per warp: m16 x n64 x k64; 32 HMMA) ----
    float sf[8][4];
#pragma unroll
    for (int nt = 0; nt < 8; nt++)
#pragma unroll
      for (int r = 0; r < 4; r++) sf[nt][r] = 0.f;
#pragma unroll
    for (int nt = 0; nt < 8; nt++) {
      const int n = nt * 8 + qr;
#pragma unroll
      for (int kc = 0; kc < 4; kc++) {
        uint32_t bfr[2];
        bfr[0] = Ks2[n * 36 + kc * 8 + qc];
        bfr[1] = Ks2[n * 36 + kc * 8 + qc + 4];
        mma_bf16(sf[nt], qf[kc], bfr);
      }
    }
    if (L < 64) {
#pragma unroll
      for (int nt = 0; nt < 8; nt++) {
        const int c0 = nt * 8 + 2 * qc;
        if (c0 >= L)     { sf[nt][0] = -1e30f; sf[nt][2] = -1e30f; }
        if (c0 + 1 >= L) { sf[nt][1] = -1e30f; sf[nt][3] = -1e30f; }
      }
    }

    // ---- online softmax on c-fragments (thread owns rows qr, qr+8) ----
    {
      float mx0 = -INFINITY, mx1 = -INFINITY;
#pragma unroll
      for (int nt = 0; nt < 8; nt++) {
        mx0 = fmaxf(mx0, fmaxf(sf[nt][0], sf[nt][1]));
        mx1 = fmaxf(mx1, fmaxf(sf[nt][2], sf[nt][3]));
      }
      mx0 = fmaxf(mx0, __shfl_xor_sync(0xffffffffu, mx0, 1));
      mx0 = fmaxf(mx0, __shfl_xor_sync(0xffffffffu, mx0, 2));
      mx1 = fmaxf(mx1, __shfl_xor_sync(0xffffffffu, mx1, 1));
      mx1 = fmaxf(mx1, __shfl_xor_sync(0xffffffffu, mx1, 2));
      const float mn0 = fmaxf(mr0, mx0), mn1 = fmaxf(mr1, mx1);
      const float a0 = __expf(mr0 - mn0), a1 = __expf(mr1 - mn1);
      mr0 = mn0; mr1 = mn1;
      float rs0 = 0.f, rs1 = 0.f;
#pragma unroll
      for (int nt = 0; nt < 8; nt++) {
        sf[nt][0] = __expf(sf[nt][0] - mn0); rs0 += sf[nt][0];
        sf[nt][1] = __expf(sf[nt][1] - mn0); rs0 += sf[nt][1];
        sf[nt][2] = __expf(sf[nt][2] - mn1); rs1 += sf[nt][2];
        sf[nt][3] = __expf(sf[nt][3] - mn1); rs1 += sf[nt][3];
      }
      rs0 += __shfl_xor_sync(0xffffffffu, rs0, 1);
      rs0 += __shfl_xor_sync(0xffffffffu, rs0, 2);
      rs1 += __shfl_xor_sync(0xffffffffu, rs1, 1);
      rs1 += __shfl_xor_sync(0xffffffffu, rs1, 2);
      lr0 = lr0 * a0 + rs0;
      lr1 = lr1 * a1 + rs1;
#pragma unroll
      for (int nt = 0; nt < 8; nt++) {
        oacc[nt][0] *= a0; oacc[nt][1] *= a0;
        oacc[nt][2] *= a1; oacc[nt][3] *= a1;
      }
    }

    // ---- O += P @ Vn : P stays in registers (S C-frag == PV A-frag) ----
#pragma unroll
    for (int kt = 0; kt < 4; kt++) {
      uint32_t pa[4];
      pa[0] = bfpack(sf[2 * kt][0],     sf[2 * kt][1]);
      pa[1] = bfpack(sf[2 * kt][2],     sf[2 * kt][3]);
      pa[2] = bfpack(sf[2 * kt + 1][0], sf[2 * kt + 1][1]);
      pa[3] = bfpack(sf[2 * kt + 1][2], sf[2 * kt + 1][3]);
#pragma unroll
      for (int nt = 0; nt < 8; nt++) {
        const int n = nt * 8 + qr;
        const int swz = nt << 2;
        uint32_t bfr[2];
        bfr[0] = Vt2[n * 36 + ((kt * 8 + qc) ^ swz)];
        bfr[1] = Vt2[n * 36 + ((kt * 8 + qc + 4) ^ swz)];
        mma_bf16(oacc[nt], pa, bfr);
      }
    }
  }

  // ---- epilogue: normalize, write g_attn16 [b,n,h*d] as bf16 ----
  {
    const float i0 = 1.0f / lr0, i1 = 1.0f / lr1;
    const size_t r0 = (size_t)(b * kN + qt * 128 + warp * 16 + qr);
    uint32_t* out = (uint32_t*)g_attn16;
#pragma unroll
    for (int nt = 0; nt < 8; nt++) {
      const int col = h * 64 + nt * 8 + 2 * qc;
      out[(r0 * kDim + col) >> 1] = bfpack(oacc[nt][0] * i0, oacc[nt][1] * i0);
      out[((r0 + 8) * kDim + col) >> 1] = bfpack(oacc[nt][2] * i1, oacc[nt][3] * i1);
    }
  }
}

// ---------------- launch ----------------
extern "C" void kernel_launch(void* const* d_in, const int* in_sizes, int n_in,
                              void* d_out, int out_size) {
  const float *x = nullptr, *wq = nullptr, *wo = nullptr, *mkv = nullptr;
  for (int i = 0; i < n_in; i++) {
    switch (in_sizes[i]) {
      case kRows * kDim:        x   = (const float*)d_in[i]; break;  // 4194304
      case kQkvN * kDim:        wq  = (const float*)d_in[i]; break;  // 3145728
      case kDim * kDim:         wo  = (const float*)d_in[i]; break;  // 1048576
      case 2 * kHeads * 4 * kD: mkv = (const float*)d_in[i]; break;  // 8192
    }
  }
  if (!x || !wq || !wo || !mkv) return;

  static bool attr_set = false;
  if (!attr_set) {
    cudaFuncSetAttribute(gemm_bf16_kernel<kQkvN, false>,
                         cudaFuncAttributeMaxDynamicSharedMemorySize, kGemmSmemBytes);
    cudaFuncSetAttribute(gemm_bf16_kernel<kDim, true>,
                         cudaFuncAttributeMaxDynamicSharedMemorySize, kGemmSmemBytes);
    cudaFuncSetAttribute(attn_kernel,
                         cudaFuncAttributeMaxDynamicSharedMemorySize, kAttnSmemBytes);
    attr_set = true;
  }

  conv_x_kernel<<<kRows * kDim / 1024, 256>>>(x);
  norm_rows_kernel<<<kQkvN, 256>>>(wq, 0);
  norm_rows_kernel<<<kDim, 256>>>(wo, 1);

  // qkv = x16 @ wn_qkv16^T  (fp32 accumulate/output)
  {
    __nv_bfloat16 *xin, *wnq;
    float* qkvp;
    cudaGetSymbolAddress((void**)&xin, g_x16);
    cudaGetSymbolAddress((void**)&wnq, g_wn_qkv16);
    cudaGetSymbolAddress((void**)&qkvp, g_qkv);
    gemm_bf16_kernel<kQkvN, false><<<dim3(kQkvN / 128, kRows / 128), 256, kGemmSmemBytes>>>(
        xin, wnq, qkvp, nullptr);
  }

  attn_kernel<<<dim3(kN / 128, kB * kHeads), 256, kAttnSmemBytes>>>(mkv);

  // out = (attn16 @ wn_out16^T) * c_out + x * c_x
  {
    __nv_bfloat16 *attn_in, *wno;
    cudaGetSymbolAddress((void**)&attn_in, g_attn16);
    cudaGetSymbolAddress((void**)&wno, g_wn_out16);
    gemm_bf16_kernel<kDim, true><<<dim3(kDim / 128, kRows / 128), 256, kGemmSmemBytes>>>(
        attn_in, wno, (float*)d_out, x);
  }
}

// round 17
// speedup vs baseline: 1.4620x; 1.4620x over previous
#include <cuda_runtime.h>
#include <cuda_bf16.h>
#include <math.h>
#include <stdint.h>

static constexpr int kHeads = 16;
static constexpr int kD     = 64;
static constexpr int kB     = 2;
static constexpr int kN     = 2048;
static constexpr int kDim   = 1024;
static constexpr int kRows  = kB * kN;          // 4096
static constexpr int kQkvN  = 3 * kHeads * kD;  // 3072
static constexpr int kKV    = kN + 4;           // 2052

// ---------------- scratch (device globals; no allocation) ----------------
__device__ __nv_bfloat16 g_x16[(size_t)kRows * kDim];
__device__ __nv_bfloat16 g_wn_qkv16[(size_t)kQkvN * kDim];
__device__ __nv_bfloat16 g_wn_out16[(size_t)kDim * kDim];
__device__ __nv_bfloat16 g_attn16[(size_t)kRows * kDim];
__device__ float g_qkv[(size_t)kRows * kQkvN];

__device__ __forceinline__ uint32_t bfpack(float lo, float hi) {
  uint32_t r;
  asm("cvt.rn.bf16x2.f32 %0, %1, %2;" : "=r"(r) : "f"(hi), "f"(lo));
  return r;
}

__device__ __forceinline__ void cp16(uint32_t* s, const void* g) {
  uint32_t sa = (uint32_t)__cvta_generic_to_shared(s);
  asm volatile("cp.async.cg.shared.global [%0], [%1], 16;\n" :: "r"(sa), "l"(g));
}

__device__ __forceinline__ void mma_bf16(float* d, const uint32_t* a, const uint32_t* b) {
  asm volatile(
      "mma.sync.aligned.m16n8k16.row.col.f32.bf16.bf16.f32 "
      "{%0,%1,%2,%3}, {%4,%5,%6,%7}, {%8,%9}, {%0,%1,%2,%3};\n"
      : "+f"(d[0]), "+f"(d[1]), "+f"(d[2]), "+f"(d[3])
      : "r"(a[0]), "r"(a[1]), "r"(a[2]), "r"(a[3]), "r"(b[0]), "r"(b[1]));
}

__device__ __forceinline__ void ldsm4(uint32_t* r, uint32_t addr) {
  asm volatile("ldmatrix.sync.aligned.m8n8.x4.shared.b16 {%0,%1,%2,%3}, [%4];"
               : "=r"(r[0]), "=r"(r[1]), "=r"(r[2]), "=r"(r[3]) : "r"(addr));
}

// ---------------- convert x to bf16 ----------------
__global__ __launch_bounds__(256) void conv_x_kernel(const float* __restrict__ x) {
  const int i = blockIdx.x * 256 + threadIdx.x;  // one float4 each
  float4 v = ((const float4*)x)[i];
  ((uint2*)g_x16)[i] = make_uint2(bfpack(v.x, v.y), bfpack(v.z, v.w));
}

// ---------------- weight row l2-norm -> bf16 ----------------
__global__ __launch_bounds__(256) void norm_rows_kernel(const float* __restrict__ w, int which) {
  __nv_bfloat16* wn = which ? g_wn_out16 : g_wn_qkv16;
  const int row = blockIdx.x;
  const int t = threadIdx.x;  // 256 threads, 1024 cols -> 1 float4 each
  float4 v = ((const float4*)(w + (size_t)row * kDim))[t];
  float ss = v.x * v.x + v.y * v.y + v.z * v.z + v.w * v.w;
#pragma unroll
  for (int off = 16; off; off >>= 1) ss += __shfl_xor_sync(0xffffffffu, ss, off);
  __shared__ float red[8];
  if ((t & 31) == 0) red[t >> 5] = ss;
  __syncthreads();
  float tot = red[0] + red[1] + red[2] + red[3] + red[4] + red[5] + red[6] + red[7];
  float sc = 1.0f / (fmaxf(sqrtf(tot), 1e-4f) * 32.0f);  // 32 = sqrt(1024)
  ((uint2*)(wn + (size_t)row * kDim))[t] =
      make_uint2(bfpack(v.x * sc, v.y * sc), bfpack(v.z * sc, v.w * sc));
}

// ---------------- bf16 tensor-core GEMM: C[m,n] = sum_k A[m,k]*B[n,k] ----------------
// (R15 measured-best: 128x128 CTA tile, BK=64 halves, 2-stage cp.async,
// 8 warps (2x4), warp tile 64x32 = 4x4 m16n8k16 frags via ldmatrix.x4,
// stride 36 uints -> conflict-free.)
static constexpr int kGemmSmemBytes = 4 * 4608 * 4;  // 73728

template <int NCOLS, bool FUSE>
__global__ __launch_bounds__(256, 2) void gemm_bf16_kernel(const __nv_bfloat16* __restrict__ A,
                                                           const __nv_bfloat16* __restrict__ Bw,
                                                           float* __restrict__ C,
                                                           const float* __restrict__ resid) {
  extern __shared__ uint32_t sg[];
  uint32_t* AsBuf[2] = {sg, sg + 4608};
  uint32_t* BsBuf[2] = {sg + 9216, sg + 13824};

  const int t = threadIdx.x, lane = t & 31, warp = t >> 5;
  const int wm = warp >> 2, wn = warp & 3;
  const int m0 = blockIdx.y * 128, n0 = blockIdx.x * 128;
  const int srow = t >> 1, sc2 = (t & 1) * 16;  // half2 col offset
  const __nv_bfloat16* gA = A + (size_t)(m0 + srow) * kDim + sc2 * 2;
  const __nv_bfloat16* gB = Bw + (size_t)(n0 + srow) * kDim + sc2 * 2;

  auto prefetch = [&](int s, int k0) {  // k0 in halves
    uint32_t* da = AsBuf[s] + srow * 36 + sc2;
    uint32_t* db = BsBuf[s] + srow * 36 + sc2;
#pragma unroll
    for (int u = 0; u < 4; u++) {
      cp16(da + u * 4, gA + k0 + u * 8);
      cp16(db + u * 4, gB + k0 + u * 8);
    }
  };

  float acc[4][4][4];
#pragma unroll
  for (int mt = 0; mt < 4; mt++)
#pragma unroll
    for (int nt = 0; nt < 4; nt++)
#pragma unroll
      for (int r = 0; r < 4; r++) acc[mt][nt][r] = 0.f;

  prefetch(0, 0);
  asm volatile("cp.async.commit_group;\n");

  const int qr = lane >> 2, qc = lane & 3;
  // ldmatrix lane offsets (uint units, relative to tile base):
  const int a_off = (wm * 64 + (lane & 7) + ((lane >> 3) & 1) * 8) * 36 + (lane >> 4) * 4;
  const int b_off = (wn * 32 + (lane & 7) + ((lane >> 4) & 1) * 8) * 36 + ((lane >> 3) & 1) * 4;

#pragma unroll 1
  for (int kb = 0; kb < 16; kb++) {  // 16 x 64 halves = 1024
    const int cur = kb & 1;
    if (kb < 15) {
      prefetch(cur ^ 1, (kb + 1) * 64);
      asm volatile("cp.async.commit_group;\n");
      asm volatile("cp.async.wait_group 1;\n");
    } else {
      asm volatile("cp.async.wait_group 0;\n");
    }
    __syncthreads();

    const uint32_t baseA = (uint32_t)__cvta_generic_to_shared(AsBuf[cur]);
    const uint32_t baseB = (uint32_t)__cvta_generic_to_shared(BsBuf[cur]);
#pragma unroll
    for (int kt = 0; kt < 4; kt++) {  // 4 x k16
      uint32_t af[4][4], bq[2][4];
      ldsm4(bq[0], baseB + 4u * (b_off + kt * 8));
      ldsm4(bq[1], baseB + 4u * (b_off + 16 * 36 + kt * 8));
#pragma unroll
      for (int mt = 0; mt < 4; mt++)
        ldsm4(af[mt], baseA + 4u * (a_off + mt * 16 * 36 + kt * 8));
#pragma unroll
      for (int mt = 0; mt < 4; mt++)
#pragma unroll
        for (int nt = 0; nt < 4; nt++)
          mma_bf16(acc[mt][nt], af[mt], &bq[nt >> 1][(nt & 1) * 2]);
    }
    __syncthreads();
  }

  const float C_OUT = 0.91914503001805780f;  // 0.7/sqrt(0.58)
  const float C_X   = 0.39391929857916763f;  // 0.3/sqrt(0.58)
#pragma unroll
  for (int mt = 0; mt < 4; mt++)
#pragma unroll
    for (int nt = 0; nt < 4; nt++) {
      const int r = m0 + wm * 64 + mt * 16 + qr;
      const int cb = n0 + wn * 32 + nt * 8 + qc * 2;
      const float* a4 = acc[mt][nt];
      if (FUSE) {
        float2 r0 = *(const float2*)&resid[(size_t)r * NCOLS + cb];
        float2 r1 = *(const float2*)&resid[(size_t)(r + 8) * NCOLS + cb];
        *(float2*)&C[(size_t)r * NCOLS + cb] =
            make_float2(a4[0] * C_OUT + r0.x * C_X, a4[1] * C_OUT + r0.y * C_X);
        *(float2*)&C[(size_t)(r + 8) * NCOLS + cb] =
            make_float2(a4[2] * C_OUT + r1.x * C_X, a4[3] * C_OUT + r1.y * C_X);
      } else {
        *(float2*)&C[(size_t)r * NCOLS + cb] = make_float2(a4[0], a4[1]);
        *(float2*)&C[(size_t)(r + 8) * NCOLS + cb] = make_float2(a4[2], a4[3]);
      }
    }
}

// ---------------- bf16 tensor-core flash attention, pixel-norm fused ----------------
// (R14 measured-best structure: blocking KV loads, TLP hides latency.)
static constexpr int kAttnSmemBytes = 4608 * 4;  // 18432

__global__ __launch_bounds__(256, 2) void attn_kernel(const float* __restrict__ memkv) {
  extern __shared__ uint32_t su[];  // 4608 uints
  uint32_t* Ks2 = su;          // [64][36]
  uint32_t* Vt2 = su + 2304;   // [64][36]

  const float* __restrict__ qkv = g_qkv;
  const int t = threadIdx.x;
  const int lane = t & 31, warp = t >> 5;
  const int qr = lane >> 2, qc = lane & 3;
  const int qt = blockIdx.x;
  const int b = blockIdx.y >> 4, h = blockIdx.y & 15;

  // ---- stage + pixel-norm Q (128 rows x 32 half2, stride 36, spans Ks2+Vt2) ----
  {
    const int rr = t >> 1, half = t & 1;  // 2 threads per row, 32 cols each
    const float* qp = qkv + (size_t)(b * kN + qt * 128 + rr) * kQkvN + h * 64 + half * 32;
    float4 q4[8];
    float ss = 0.f;
#pragma unroll
    for (int u = 0; u < 8; u++) {
      q4[u] = *(const float4*)(qp + u * 4);
      ss += q4[u].x * q4[u].x + q4[u].y * q4[u].y + q4[u].z * q4[u].z + q4[u].w * q4[u].w;
    }
    ss += __shfl_xor_sync(0xffffffffu, ss, 1);
    const float sc = 1.0f / fmaxf(sqrtf(ss), 1e-4f);
    uint32_t* dst = su + rr * 36 + half * 16;
#pragma unroll
    for (int u = 0; u < 4; u++) {
      uint4 pk;
      pk.x = bfpack(q4[u * 2].x * sc, q4[u * 2].y * sc);
      pk.y = bfpack(q4[u * 2].z * sc, q4[u * 2].w * sc);
      pk.z = bfpack(q4[u * 2 + 1].x * sc, q4[u * 2 + 1].y * sc);
      pk.w = bfpack(q4[u * 2 + 1].z * sc, q4[u * 2 + 1].w * sc);
      *(uint4*)(dst + u * 4) = pk;
    }
  }
  __syncthreads();

  // ---- Q A-fragments -> registers (held for entire kernel) ----
  uint32_t qf[4][4];
  {
    const int m = warp * 16 + qr;
#pragma unroll
    for (int kc = 0; kc < 4; kc++) {
      qf[kc][0] = su[m * 36 + kc * 8 + qc];
      qf[kc][1] = su[(m + 8) * 36 + kc * 8 + qc];
      qf[kc][2] = su[m * 36 + kc * 8 + qc + 4];
      qf[kc][3] = su[(m + 8) * 36 + kc * 8 + qc + 4];
    }
  }

  float oacc[8][4];
#pragma unroll
  for (int nt = 0; nt < 8; nt++)
#pragma unroll
    for (int r = 0; r < 4; r++) oacc[nt][r] = 0.f;
  float mr0 = -INFINITY, mr1 = -INFINITY, lr0 = 0.f, lr1 = 0.f;

  const int pr = t >> 3, lq8 = t & 7;  // kv loader: pair row 0..31, 8 d-threads/row

  for (int j0 = 0; j0 < kKV; j0 += 64) {
    const int L = (kKV - j0 < 64) ? (kKV - j0) : 64;

    // load two adjacent kv rows (2pr, 2pr+1), 8 d values each at d0 = lq8*8
    float ka[8], kb8[8], va[8], vb[8];
    float sska = 0.f, sskb = 0.f, ssva = 0.f, ssvb = 0.f;
    auto loadrow = [&](int j, float* kk, float* vv, float& ssk, float& ssv) {
      if (j < kKV) {
        const float *kp, *vp;
        if (j < 4) {
          kp = memkv + (size_t)(h * 4 + j) * 64 + lq8 * 8;
          vp = memkv + (size_t)((kHeads + h) * 4 + j) * 64 + lq8 * 8;
        } else {
          const size_t base = (size_t)(b * kN + (j - 4)) * kQkvN + h * 64 + lq8 * 8;
          kp = qkv + base + 1024;
          vp = qkv + base + 2048;
        }
#pragma unroll
        for (int u = 0; u < 2; u++) {
          float4 k4 = *(const float4*)(kp + u * 4);
          float4 v4 = *(const float4*)(vp + u * 4);
          kk[u * 4 + 0] = k4.x; kk[u * 4 + 1] = k4.y; kk[u * 4 + 2] = k4.z; kk[u * 4 + 3] = k4.w;
          vv[u * 4 + 0] = v4.x; vv[u * 4 + 1] = v4.y; vv[u * 4 + 2] = v4.z; vv[u * 4 + 3] = v4.w;
          ssk += k4.x * k4.x + k4.y * k4.y + k4.z * k4.z + k4.w * k4.w;
          ssv += v4.x * v4.x + v4.y * v4.y + v4.z * v4.z + v4.w * v4.w;
        }
      } else {
#pragma unroll
        for (int u = 0; u < 8; u++) { kk[u] = 0.f; vv[u] = 0.f; }
      }
    };
    loadrow(j0 + 2 * pr,     ka,  va, sska, ssva);
    loadrow(j0 + 2 * pr + 1, kb8, vb, sskb, ssvb);
#pragma unroll
    for (int off = 1; off <= 4; off <<= 1) {  // reduce over the 8 d-threads
      sska += __shfl_xor_sync(0xffffffffu, sska, off);
      sskb += __shfl_xor_sync(0xffffffffu, sskb, off);
      ssva += __shfl_xor_sync(0xffffffffu, ssva, off);
      ssvb += __shfl_xor_sync(0xffffffffu, ssvb, off);
    }
    const float ska = 8.0f / fmaxf(sqrtf(sska), 1e-4f);
    const float skb = 8.0f / fmaxf(sqrtf(sskb), 1e-4f);
    const float sva = 8.0f / fmaxf(sqrtf(ssva), 1e-4f);
    const float svb = 8.0f / fmaxf(sqrtf(ssvb), 1e-4f);

    __syncthreads();  // previous tile (or Q stage/frag reads) fully consumed
    {
      // K: row-major [kv][dpair]
      uint4 p0, p1;
      p0.x = bfpack(ka[0] * ska, ka[1] * ska);
      p0.y = bfpack(ka[2] * ska, ka[3] * ska);
      p0.z = bfpack(ka[4] * ska, ka[5] * ska);
      p0.w = bfpack(ka[6] * ska, ka[7] * ska);
      p1.x = bfpack(kb8[0] * skb, kb8[1] * skb);
      p1.y = bfpack(kb8[2] * skb, kb8[3] * skb);
      p1.z = bfpack(kb8[4] * skb, kb8[5] * skb);
      p1.w = bfpack(kb8[6] * skb, kb8[7] * skb);
      *(uint4*)(Ks2 + (2 * pr) * 36 + lq8 * 4) = p0;
      *(uint4*)(Ks2 + (2 * pr + 1) * 36 + lq8 * 4) = p1;
      // V: transposed [d][kvpair], swizzled col = pr ^ (lq8<<2)
      const int col = pr ^ (lq8 << 2);
#pragma unroll
      for (int i = 0; i < 8; i++)
        Vt2[(lq8 * 8 + i) * 36 + col] = bfpack(va[i] * sva, vb[i] * svb);
    }
    __syncthreads();

    // ---- S = Qn @ Kn^T (per warp: m16 x n64 x k64; 32 HMMA) ----
    float sf[8][4];
#pragma unroll
    for (int nt = 0; nt < 8; nt++)
#pragma unroll
      for (int r = 0; r < 4; r++) sf[nt][r] = 0.f;
#pragma unroll
    for (int nt = 0; nt < 8; nt++) {
      const int n = nt * 8 + qr;
#pragma unroll
      for (int kc = 0; kc < 4; kc++) {
        uint32_t bfr[2];
        bfr[0] = Ks2[n * 36 + kc * 8 + qc];
        bfr[1] = Ks2[n * 36 + kc * 8 + qc + 4];
        mma_bf16(sf[nt], qf[kc], bfr);
      }
    }
    if (L < 64) {
#pragma unroll
      for (int nt = 0; nt < 8; nt++) {
        const int c0 = nt * 8 + 2 * qc;
        if (c0 >= L)     { sf[nt][0] = -1e30f; sf[nt][2] = -1e30f; }
        if (c0 + 1 >= L) { sf[nt][1] = -1e30f; sf[nt][3] = -1e30f; }
      }
    }

    // ---- online softmax on c-fragments (thread owns rows qr, qr+8) ----
    {
      float mx0 = -INFINITY, mx1 = -INFINITY;
#pragma unroll
      for (int nt = 0; nt < 8; nt++) {
        mx0 = fmaxf(mx0, fmaxf(sf[nt][0], sf[nt][1]));
        mx1 = fmaxf(mx1, fmaxf(sf[nt][2], sf[nt][3]));
      }
      mx0 = fmaxf(mx0, __shfl_xor_sync(0xffffffffu, mx0, 1));
      mx0 = fmaxf(mx0, __shfl_xor_sync(0xffffffffu, mx0, 2));
      mx1 = fmaxf(mx1, __shfl_xor_sync(0xffffffffu, mx1, 1));
      mx1 = fmaxf(mx1, __shfl_xor_sync(0xffffffffu, mx1, 2));
      const float mn0 = fmaxf(mr0, mx0), mn1 = fmaxf(mr1, mx1);
      const float a0 = __expf(mr0 - mn0), a1 = __expf(mr1 - mn1);
      mr0 = mn0; mr1 = mn1;
      float rs0 = 0.f, rs1 = 0.f;
#pragma unroll
      for (int nt = 0; nt < 8; nt++) {
        sf[nt][0] = __expf(sf[nt][0] - mn0); rs0 += sf[nt][0];
        sf[nt][1] = __expf(sf[nt][1] - mn0); rs0 += sf[nt][1];
        sf[nt][2] = __expf(sf[nt][2] - mn1); rs1 += sf[nt][2];
        sf[nt][3] = __expf(sf[nt][3] - mn1); rs1 += sf[nt][3];
      }
      rs0 += __shfl_xor_sync(0xffffffffu, rs0, 1);
      rs0 += __shfl_xor_sync(0xffffffffu, rs0, 2);
      rs1 += __shfl_xor_sync(0xffffffffu, rs1, 1);
      rs1 += __shfl_xor_sync(0xffffffffu, rs1, 2);
      lr0 = lr0 * a0 + rs0;
      lr1 = lr1 * a1 + rs1;
#pragma unroll
      for (int nt = 0; nt < 8; nt++) {
        oacc[nt][0] *= a0; oacc[nt][1] *= a0;
        oacc[nt][2] *= a1; oacc[nt][3] *= a1;
      }
    }

    // ---- O += P @ Vn : P stays in registers (S C-frag == PV A-frag) ----
#pragma unroll
    for (int kt = 0; kt < 4; kt++) {
      uint32_t pa[4];
      pa[0] = bfpack(sf[2 * kt][0],     sf[2 * kt][1]);
      pa[1] = bfpack(sf[2 * kt][2],     sf[2 * kt][3]);
      pa[2] = bfpack(sf[2 * kt + 1][0], sf[2 * kt + 1][1]);
      pa[3] = bfpack(sf[2 * kt + 1][2], sf[2 * kt + 1][3]);
#pragma unroll
      for (int nt = 0; nt < 8; nt++) {
        const int n = nt * 8 + qr;
        const int swz = nt << 2;
        uint32_t bfr[2];
        bfr[0] = Vt2[n * 36 + ((kt * 8 + qc) ^ swz)];
        bfr[1] = Vt2[n * 36 + ((kt * 8 + qc + 4) ^ swz)];
        mma_bf16(oacc[nt], pa, bfr);
      }
    }
  }

  // ---- epilogue: normalize, write g_attn16 [b,n,h*d] as bf16 ----
  {
    const float i0 = 1.0f / lr0, i1 = 1.0f / lr1;
    const size_t r0 = (size_t)(b * kN + qt * 128 + warp * 16 + qr);
    uint32_t* out = (uint32_t*)g_attn16;
#pragma unroll
    for (int nt = 0; nt < 8; nt++) {
      const int col = h * 64 + nt * 8 + 2 * qc;
      out[(r0 * kDim + col) >> 1] = bfpack(oacc[nt][0] * i0, oacc[nt][1] * i0);
      out[((r0 + 8) * kDim + col) >> 1] = bfpack(oacc[nt][2] * i1, oacc[nt][3] * i1);
    }
  }
}

// ---------------- launch ----------------
extern "C" void kernel_launch(void* const* d_in, const int* in_sizes, int n_in,
                              void* d_out, int out_size) {
  const float *x = nullptr, *wq = nullptr, *wo = nullptr, *mkv = nullptr;
  for (int i = 0; i < n_in; i++) {
    switch (in_sizes[i]) {
      case kRows * kDim:        x   = (const float*)d_in[i]; break;  // 4194304
      case kQkvN * kDim:        wq  = (const float*)d_in[i]; break;  // 3145728
      case kDim * kDim:         wo  = (const float*)d_in[i]; break;  // 1048576
      case 2 * kHeads * 4 * kD: mkv = (const float*)d_in[i]; break;  // 8192
    }
  }
  if (!x || !wq || !wo || !mkv) return;

  static bool attr_set = false;
  if (!attr_set) {
    cudaFuncSetAttribute(gemm_bf16_kernel<kQkvN, false>,
                         cudaFuncAttributeMaxDynamicSharedMemorySize, kGemmSmemBytes);
    cudaFuncSetAttribute(gemm_bf16_kernel<kDim, true>,
                         cudaFuncAttributeMaxDynamicSharedMemorySize, kGemmSmemBytes);
    cudaFuncSetAttribute(attn_kernel,
                         cudaFuncAttributeMaxDynamicSharedMemorySize, kAttnSmemBytes);
    attr_set = true;
  }

  conv_x_kernel<<<kRows * kDim / 1024, 256>>>(x);
  norm_rows_kernel<<<kQkvN, 256>>>(wq, 0);
  norm_rows_kernel<<<kDim, 256>>>(wo, 1);

  // qkv = x16 @ wn_qkv16^T  (fp32 accumulate/output)
  {
    __nv_bfloat16 *xin, *wnq;
    float* qkvp;
    cudaGetSymbolAddress((void**)&xin, g_x16);
    cudaGetSymbolAddress((void**)&wnq, g_wn_qkv16);
    cudaGetSymbolAddress((void**)&qkvp, g_qkv);
    gemm_bf16_kernel<kQkvN, false><<<dim3(kQkvN / 128, kRows / 128), 256, kGemmSmemBytes>>>(
        xin, wnq, qkvp, nullptr);
  }

  attn_kernel<<<dim3(kN / 128, kB * kHeads), 256, kAttnSmemBytes>>>(mkv);

  // out = (attn16 @ wn_out16^T) * c_out + x * c_x
  {
    __nv_bfloat16 *attn_in, *wno;
    cudaGetSymbolAddress((void**)&attn_in, g_attn16);
    cudaGetSymbolAddress((void**)&wno, g_wn_out16);
    gemm_bf16_kernel<kDim, true><<<dim3(kDim / 128, kRows / 128), 256, kGemmSmemBytes>>>(
        attn_in, wno, (float*)d_out, x);
  }
}